// round 7
// baseline (speedup 1.0000x reference)
#include <cuda_runtime.h>
#include <cuda_bf16.h>

#define HH 1024
#define WW 1024

static constexpr int NBLOCKS  = 1184;
static constexpr int NTHREADS = 256;
static constexpr int RB       = 4;          // rows per work item
static constexpr int RBLK     = HH / RB;    // 256 row-blocks per plane

__device__ float        g_part[NBLOCKS];
__device__ unsigned int g_count = 0;

typedef unsigned long long ull;

__device__ __forceinline__ ull pk(float lo, float hi) {
    ull r; asm("mov.b64 %0, {%1, %2};" : "=l"(r) : "f"(lo), "f"(hi)); return r;
}
__device__ __forceinline__ ull sub2(ull a, ull b) {
    ull r; asm("sub.rn.f32x2 %0, %1, %2;" : "=l"(r) : "l"(a), "l"(b)); return r;
}
__device__ __forceinline__ ull fma2(ull a, ull b, ull c) {
    ull r; asm("fma.rn.f32x2 %0, %1, %2, %3;" : "=l"(r) : "l"(a), "l"(b), "l"(c)); return r;
}
__device__ __forceinline__ void unpk(ull v, float& lo, float& hi) {
    asm("mov.b64 {%0, %1}, %2;" : "=f"(lo), "=f"(hi) : "l"(v));
}

// Directed sum for one quad: offsets (0,1),(1,-1),(1,0),(1,1).
// Edge duplicates realized by halo value substitution (verified, rel_err=0):
//   col 0: bl:=b.x ; col W-1: cr:=c.w, br:=b.w ; rows 0/H-1: doubled horizontals.
__device__ __forceinline__ void quadd(const float4 c, float cr,
                                      const float4 b, float bl, float br,
                                      ull& acc2) {
    const ull vp01 = pk(c.x, c.y), vp23 = pk(c.z, c.w);
    ull d;
    d = sub2(vp01, pk(c.y, c.z)); acc2 = fma2(d, d, acc2);   // right
    d = sub2(vp23, pk(c.w, cr));  acc2 = fma2(d, d, acc2);
    d = sub2(vp01, pk(b.x, b.y)); acc2 = fma2(d, d, acc2);   // down
    d = sub2(vp23, pk(b.z, b.w)); acc2 = fma2(d, d, acc2);
    const ull m12 = pk(b.y, b.z);
    d = sub2(vp01, pk(bl, b.x));  acc2 = fma2(d, d, acc2);   // down-left
    d = sub2(vp23, m12);          acc2 = fma2(d, d, acc2);
    d = sub2(vp01, m12);          acc2 = fma2(d, d, acc2);   // down-right
    d = sub2(vp23, pk(b.w, br));  acc2 = fma2(d, d, acc2);
}

__device__ __forceinline__ void hdouble(const float4 c, float cr, ull& acc2) {
    ull d;
    d = sub2(pk(c.x, c.y), pk(c.y, c.z)); acc2 = fma2(d, d, acc2);
    d = sub2(pk(c.z, c.w), pk(c.w, cr));  acc2 = fma2(d, d, acc2);
}

__global__ __launch_bounds__(NTHREADS, 6)
void lap_kernel(const float* __restrict__ f, float* __restrict__ out, int total_items) {
    ull acc2 = 0;
    const int stride = gridDim.x * blockDim.x;
    const int lane = threadIdx.x & 31;

    // Work item: (plane, 4-row block, column-quad). cq fastest -> warp lanes are
    // 32 adjacent quads = 128 contiguous pixels; warp never straddles rows, and
    // all lanes share rb/pl (stride is a multiple of 256).
    for (int t = blockIdx.x * blockDim.x + threadIdx.x; t < total_items; t += stride) {
        const int cq = t & 255;
        const int rb = (t >> 8) & (RBLK - 1);
        const int pl = t >> 16;
        const float* __restrict__ p =
            f + ((size_t)pl << 20) + ((size_t)(rb * RB) << 10) + (cq << 2);
        const bool eL = (cq == 0), eR = (cq == 255);

        if (rb < RBLK - 1) {
            // ---- front-batched loads: 5 vector LDGs, branch-free ----
            float4 r[RB + 1];
            #pragma unroll
            for (int k = 0; k <= RB; k++)
                r[k] = *(const float4*)(p + ((size_t)k << 10));

            // lane-31 right halos / lane-0 left halos (predicated scalar batch)
            float hr[RB + 1], hl[RB + 1];
            if (lane == 31 && !eR) {
                #pragma unroll
                for (int k = 0; k <= RB; k++) hr[k] = p[((size_t)k << 10) + 4];
            }
            if (lane == 0 && !eL) {
                #pragma unroll
                for (int k = 1; k <= RB; k++) hl[k] = p[((size_t)k << 10) - 1];
            }

            float rh[RB + 1], lh[RB + 1];
            #pragma unroll
            for (int k = 0; k <= RB; k++) {
                const float sd = __shfl_down_sync(0xffffffffu, r[k].x, 1);
                rh[k] = (lane == 31) ? (eR ? r[k].w : hr[k]) : sd;
            }
            #pragma unroll
            for (int k = 1; k <= RB; k++) {
                const float su = __shfl_up_sync(0xffffffffu, r[k].w, 1);
                lh[k] = (lane == 0) ? (eL ? r[k].x : hl[k]) : su;
            }

            #pragma unroll
            for (int k = 0; k < RB; k++)
                quadd(r[k], rh[k], r[k + 1], lh[k + 1], rh[k + 1], acc2);

            if (rb == 0) hdouble(r[0], rh[0], acc2);   // top row doubled horizontals
        } else {
            // ---- bottom block: rows H-4..H-1 (4 loads, 3 quadds, doubled bottom) ----
            float4 r[RB];
            #pragma unroll
            for (int k = 0; k < RB; k++)
                r[k] = *(const float4*)(p + ((size_t)k << 10));

            float hr[RB], hl[RB];
            if (lane == 31 && !eR) {
                #pragma unroll
                for (int k = 0; k < RB; k++) hr[k] = p[((size_t)k << 10) + 4];
            }
            if (lane == 0 && !eL) {
                #pragma unroll
                for (int k = 1; k < RB; k++) hl[k] = p[((size_t)k << 10) - 1];
            }

            float rh[RB], lh[RB];
            #pragma unroll
            for (int k = 0; k < RB; k++) {
                const float sd = __shfl_down_sync(0xffffffffu, r[k].x, 1);
                rh[k] = (lane == 31) ? (eR ? r[k].w : hr[k]) : sd;
            }
            #pragma unroll
            for (int k = 1; k < RB; k++) {
                const float su = __shfl_up_sync(0xffffffffu, r[k].w, 1);
                lh[k] = (lane == 0) ? (eL ? r[k].x : hl[k]) : su;
            }

            #pragma unroll
            for (int k = 0; k < RB - 1; k++)
                quadd(r[k], rh[k], r[k + 1], lh[k + 1], rh[k + 1], acc2);

            hdouble(r[RB - 1], rh[RB - 1], acc2);      // bottom row doubled horizontals
        }
    }

    float lo, hi; unpk(acc2, lo, hi);
    float acc = lo + hi;

    // ---- deterministic block reduction ----
    __shared__ float swarp[NTHREADS / 32];
    #pragma unroll
    for (int o = 16; o > 0; o >>= 1)
        acc += __shfl_down_sync(0xffffffffu, acc, o);
    if ((threadIdx.x & 31) == 0) swarp[threadIdx.x >> 5] = acc;
    __syncthreads();
    if (threadIdx.x < NTHREADS / 32) {
        float v = swarp[threadIdx.x];
        #pragma unroll
        for (int o = NTHREADS / 64; o > 0; o >>= 1)
            v += __shfl_down_sync(0xffu, v, o);
        if (threadIdx.x == 0) g_part[blockIdx.x] = v;
    }

    // ---- last-block final reduction ----
    __shared__ bool isLast;
    if (threadIdx.x == 0) {
        __threadfence();
        isLast = (atomicAdd(&g_count, 1u) == (unsigned)gridDim.x - 1u);
    }
    __syncthreads();
    if (isLast) {
        volatile float* gp = g_part;
        double v = 0.0;
        for (int idx = threadIdx.x; idx < NBLOCKS; idx += NTHREADS) v += (double)gp[idx];
        __shared__ double sd[NTHREADS];
        sd[threadIdx.x] = v;
        __syncthreads();
        #pragma unroll
        for (int o = NTHREADS / 2; o > 0; o >>= 1) {
            if (threadIdx.x < o) sd[threadIdx.x] += sd[threadIdx.x + o];
            __syncthreads();
        }
        if (threadIdx.x == 0) {
            out[0] = (float)(2.0 * sd[0]);
            g_count = 0;
        }
    }
}

extern "C" void kernel_launch(void* const* d_in, const int* in_sizes, int n_in,
                              void* d_out, int out_size) {
    const float* f = (const float*)d_in[0];
    const int n = in_sizes[0];
    const int planes = n >> 20;                 // 48
    const int total_items = planes << 16;       // planes * RBLK(256) * 256 quads
    lap_kernel<<<NBLOCKS, NTHREADS>>>(f, (float*)d_out, total_items);
}

// round 8
// speedup vs baseline: 1.6214x; 1.6214x over previous
#include <cuda_runtime.h>
#include <cuda_bf16.h>

#define HH 1024
#define WW 1024

static constexpr int NBLOCKS  = 1184;
static constexpr int NTHREADS = 256;

__device__ float        g_part[NBLOCKS];
__device__ unsigned int g_count = 0;

typedef unsigned long long ull;

__device__ __forceinline__ ull pk(float lo, float hi) {
    ull r; asm("mov.b64 %0, {%1, %2};" : "=l"(r) : "f"(lo), "f"(hi)); return r;
}
__device__ __forceinline__ ull sub2(ull a, ull b) {
    ull r; asm("sub.rn.f32x2 %0, %1, %2;" : "=l"(r) : "l"(a), "l"(b)); return r;
}
__device__ __forceinline__ ull fma2(ull a, ull b, ull c) {
    ull r; asm("fma.rn.f32x2 %0, %1, %2, %3;" : "=l"(r) : "l"(a), "l"(b), "l"(c)); return r;
}
__device__ __forceinline__ void unpk(ull v, float& lo, float& hi) {
    asm("mov.b64 {%0, %1}, %2;" : "=f"(lo), "=f"(hi) : "l"(v));
}

// total = 2 * S: directed offsets {(0,1),(1,-1),(1,0),(1,1)} with clamped-edge
// duplicates realized by halo value substitution (verified, rel_err=0):
//   col 0: bl:=b.x ; col W-1: cr:=c.w, br:=b.w ; rows 0/H-1: doubled horizontals.
__device__ __forceinline__ void quadd(const float4 c, float cr,
                                      const float4 b, float bl, float br,
                                      ull& acc2) {
    const ull vp01 = pk(c.x, c.y), vp23 = pk(c.z, c.w);
    ull d;
    d = sub2(vp01, pk(c.y, c.z)); acc2 = fma2(d, d, acc2);   // right
    d = sub2(vp23, pk(c.w, cr));  acc2 = fma2(d, d, acc2);
    d = sub2(vp01, pk(b.x, b.y)); acc2 = fma2(d, d, acc2);   // down
    d = sub2(vp23, pk(b.z, b.w)); acc2 = fma2(d, d, acc2);
    const ull m12 = pk(b.y, b.z);
    d = sub2(vp01, pk(bl, b.x));  acc2 = fma2(d, d, acc2);   // down-left
    d = sub2(vp23, m12);          acc2 = fma2(d, d, acc2);
    d = sub2(vp01, m12);          acc2 = fma2(d, d, acc2);   // down-right
    d = sub2(vp23, pk(b.w, br));  acc2 = fma2(d, d, acc2);
}

__global__ __launch_bounds__(NTHREADS)
void lap_kernel(const float* __restrict__ f, float* __restrict__ out, int total_rows) {
    ull acc2 = 0;
    const int lane = threadIdx.x & 31;
    const int t0 = blockIdx.x * blockDim.x + threadIdx.x;

    // stride (1184*256) is a multiple of 256 quads/row -> each thread keeps the
    // SAME column-quad forever and steps down rstep rows per iteration. All
    // column-related math is loop-invariant and hoisted here.
    const int  jq     = t0 & 255;
    const bool firstq = (jq == 0);
    const bool lastq  = (jq == 255);
    const bool ln31   = (lane == 31);
    const bool ln0    = (lane == 0);
    const int  rstep  = (NBLOCKS * NTHREADS) >> 8;   // 1184 rows/step
    const float* __restrict__ colp = f + (jq << 2);

    for (int rq = t0 >> 8; rq < total_rows; rq += rstep) {
        const int i = rq & (HH - 1);
        const float* __restrict__ cur = colp + ((size_t)rq << 10);

        if (i < HH - 1) {
            const float* __restrict__ nxt = cur + WW;
            const float4 c = *(const float4*)cur;
            const float4 b = *(const float4*)nxt;

            float cr = __shfl_down_sync(0xffffffffu, c.x, 1);
            float br = __shfl_down_sync(0xffffffffu, b.x, 1);
            float bl = __shfl_up_sync  (0xffffffffu, b.w, 1);
            if (ln31) {
                if (lastq) { cr = c.w; br = b.w; }       // col W-1 substitutions
                else       { cr = cur[4]; br = nxt[4]; }
            }
            if (ln0) bl = firstq ? b.x : nxt[-1];        // col 0 substitution

            quadd(c, cr, b, bl, br, acc2);

            if (i == 0) {   // top row: horizontal pairs count double (add once more)
                ull d;
                d = sub2(pk(c.x, c.y), pk(c.y, c.z)); acc2 = fma2(d, d, acc2);
                d = sub2(pk(c.z, c.w), pk(c.w, cr));  acc2 = fma2(d, d, acc2);
            }
        } else {
            // bottom row: horizontal pairs only, counted double
            const float4 c = *(const float4*)cur;
            float cr = __shfl_down_sync(0xffffffffu, c.x, 1);
            if (ln31) cr = lastq ? c.w : cur[4];
            ull d;
            d = sub2(pk(c.x, c.y), pk(c.y, c.z));
            acc2 = fma2(d, d, acc2); acc2 = fma2(d, d, acc2);
            d = sub2(pk(c.z, c.w), pk(c.w, cr));
            acc2 = fma2(d, d, acc2); acc2 = fma2(d, d, acc2);
        }
    }

    float lo, hi; unpk(acc2, lo, hi);
    float acc = lo + hi;

    // ---- deterministic block reduction ----
    __shared__ float swarp[NTHREADS / 32];
    #pragma unroll
    for (int o = 16; o > 0; o >>= 1)
        acc += __shfl_down_sync(0xffffffffu, acc, o);
    if ((threadIdx.x & 31) == 0) swarp[threadIdx.x >> 5] = acc;
    __syncthreads();
    if (threadIdx.x < NTHREADS / 32) {
        float v = swarp[threadIdx.x];
        #pragma unroll
        for (int o = NTHREADS / 64; o > 0; o >>= 1)
            v += __shfl_down_sync(0xffu, v, o);
        if (threadIdx.x == 0) g_part[blockIdx.x] = v;
    }

    // ---- last-block final reduction ----
    __shared__ bool isLast;
    if (threadIdx.x == 0) {
        __threadfence();
        isLast = (atomicAdd(&g_count, 1u) == (unsigned)gridDim.x - 1u);
    }
    __syncthreads();
    if (isLast) {
        volatile float* gp = g_part;
        double v = 0.0;
        for (int idx = threadIdx.x; idx < NBLOCKS; idx += NTHREADS) v += (double)gp[idx];
        __shared__ double sd[NTHREADS];
        sd[threadIdx.x] = v;
        __syncthreads();
        #pragma unroll
        for (int o = NTHREADS / 2; o > 0; o >>= 1) {
            if (threadIdx.x < o) sd[threadIdx.x] += sd[threadIdx.x + o];
            __syncthreads();
        }
        if (threadIdx.x == 0) {
            out[0] = (float)(2.0 * sd[0]);
            g_count = 0;
        }
    }
}

extern "C" void kernel_launch(void* const* d_in, const int* in_sizes, int n_in,
                              void* d_out, int out_size) {
    const float* f = (const float*)d_in[0];
    const int n = in_sizes[0];
    const int total_rows = n >> 10;   // planes * H = 49152
    lap_kernel<<<NBLOCKS, NTHREADS>>>(f, (float*)d_out, total_rows);
}